// round 1
// baseline (speedup 1.0000x reference)
#include <cuda_runtime.h>
#include <cuda_bf16.h>

// ---------------------------------------------------------------------------
// NeuralODE: y' = tanh(y@W1+b1)@W2+b2, Dopri5 fixed step dt0 (Hairer initial
// step from row 0), integrate to T = t/10, out = stack([x, yT]).
// Row-independent dynamics -> one persistent fused kernel, weights + state in
// SMEM, bf16 mma.sync GEMMs with fp32 state/accumulators.
// ---------------------------------------------------------------------------

#define PADK 136  // bf16 row stride: 68 words, 68 % 32 == 4 -> conflict-free frags

struct Smem {
    float y[64][128];                     // fp32 state
    float b1s[128];
    float b2s[128];
    __nv_bfloat16 Wt1[128][PADK];         // W1 transposed: Wt1[n][k] = W1[k][n]
    __nv_bfloat16 Wt2[128][PADK];
    __nv_bfloat16 kbuf[5][64][PADK];      // k1..k5 (k6 stays in registers)
    __nv_bfloat16 Abuf[64][PADK];         // stage arg / hidden buffer
};

__device__ float g_dt0;

__device__ __forceinline__ float tanh_fast(float x) {
    float r;
    asm("tanh.approx.f32 %0, %1;" : "=f"(r) : "f"(x));
    return r;
}

__device__ __forceinline__ void mma_bf16(float* c, const unsigned* a, const unsigned* b) {
    asm volatile(
        "mma.sync.aligned.m16n8k16.row.col.f32.bf16.bf16.f32 "
        "{%0,%1,%2,%3}, {%4,%5,%6,%7}, {%8,%9}, {%0,%1,%2,%3};"
        : "+f"(c[0]), "+f"(c[1]), "+f"(c[2]), "+f"(c[3])
        : "r"(a[0]), "r"(a[1]), "r"(a[2]), "r"(a[3]), "r"(b[0]), "r"(b[1]));
}

// C[16x64 at (m0,n0)] = A[16x128 at m0] @ Wt^T + bias, warp-collective.
__device__ __forceinline__ void gemm_tile(float c[8][4],
                                          const __nv_bfloat16 (*A)[PADK],
                                          const __nv_bfloat16 (*Wt)[PADK],
                                          const float* bias,
                                          int m0, int n0, int gm, int qn) {
#pragma unroll
    for (int nt = 0; nt < 8; nt++) {
        int n = n0 + nt * 8 + qn * 2;
        float bb0 = bias[n], bb1 = bias[n + 1];
        c[nt][0] = bb0; c[nt][1] = bb1; c[nt][2] = bb0; c[nt][3] = bb1;
    }
#pragma unroll
    for (int kk = 0; kk < 8; kk++) {
        int kb = kk * 16 + qn * 2;
        unsigned a[4];
        a[0] = *(const unsigned*)&A[m0 + gm    ][kb];
        a[1] = *(const unsigned*)&A[m0 + gm + 8][kb];
        a[2] = *(const unsigned*)&A[m0 + gm    ][kb + 8];
        a[3] = *(const unsigned*)&A[m0 + gm + 8][kb + 8];
#pragma unroll
        for (int nt = 0; nt < 8; nt++) {
            int n = n0 + nt * 8 + gm;
            unsigned b[2];
            b[0] = *(const unsigned*)&Wt[n][kb];
            b[1] = *(const unsigned*)&Wt[n][kb + 8];
            mma_bf16(c[nt], a, b);
        }
    }
}

// Stage argument: Abuf = bf16(y + dt * sum_q kc[q]*k_q), elementwise on pairs.
template <int NK>
__device__ __forceinline__ void build_arg(Smem& s, int tid, float dt, const float* kc) {
#pragma unroll
    for (int j = tid; j < 4096; j += 256) {
        int row = j >> 6;
        int col = (j & 63) * 2;
        float2 yv = *(const float2*)&s.y[row][col];
        float a0 = 0.f, a1 = 0.f;
#pragma unroll
        for (int q = 0; q < NK; q++) {
            __nv_bfloat162 kv = *(const __nv_bfloat162*)&s.kbuf[q][row][col];
            a0 += kc[q] * __bfloat162float(kv.x);
            a1 += kc[q] * __bfloat162float(kv.y);
        }
        __nv_bfloat162 o;
        o.x = __float2bfloat16(yv.x + dt * a0);
        o.y = __float2bfloat16(yv.y + dt * a1);
        *(__nv_bfloat162*)&s.Abuf[row][col] = o;
    }
}

// k = f(Abuf): GEMM1 -> tanh -> GEMM2. Result left in c (fp32 frags).
__device__ __forceinline__ void f_eval(Smem& s, float c[8][4],
                                       int m0, int n0, int gm, int qn) {
    __syncthreads();  // Abuf (stage arg) ready
    gemm_tile(c, s.Abuf, s.Wt1, s.b1s, m0, n0, gm, qn);
    __syncthreads();  // everyone done reading Abuf
#pragma unroll
    for (int nt = 0; nt < 8; nt++) {
        int n = n0 + nt * 8 + qn * 2;
        __nv_bfloat162 h0, h1;
        h0.x = __float2bfloat16(tanh_fast(c[nt][0]));
        h0.y = __float2bfloat16(tanh_fast(c[nt][1]));
        h1.x = __float2bfloat16(tanh_fast(c[nt][2]));
        h1.y = __float2bfloat16(tanh_fast(c[nt][3]));
        *(__nv_bfloat162*)&s.Abuf[m0 + gm    ][n] = h0;
        *(__nv_bfloat162*)&s.Abuf[m0 + gm + 8][n] = h1;
    }
    __syncthreads();  // hidden ready
    gemm_tile(c, s.Abuf, s.Wt2, s.b2s, m0, n0, gm, qn);
}

__device__ __forceinline__ void store_k(Smem& s, const float c[8][4], int kq,
                                        int m0, int n0, int gm, int qn) {
#pragma unroll
    for (int nt = 0; nt < 8; nt++) {
        int n = n0 + nt * 8 + qn * 2;
        __nv_bfloat162 v0, v1;
        v0.x = __float2bfloat16(c[nt][0]); v0.y = __float2bfloat16(c[nt][1]);
        v1.x = __float2bfloat16(c[nt][2]); v1.y = __float2bfloat16(c[nt][3]);
        *(__nv_bfloat162*)&s.kbuf[kq][m0 + gm    ][n] = v0;
        *(__nv_bfloat162*)&s.kbuf[kq][m0 + gm + 8][n] = v1;
    }
    __syncthreads();
}

__global__ void __launch_bounds__(256, 1)
ode_kernel(const float* __restrict__ t, const float* __restrict__ x,
           const float* __restrict__ W1, const float* __restrict__ b1,
           const float* __restrict__ W2, const float* __restrict__ b2,
           float* __restrict__ out) {
    extern __shared__ unsigned char smem_raw[];
    Smem& s = *reinterpret_cast<Smem*>(smem_raw);
    const int tid = threadIdx.x;
    const int row0 = blockIdx.x * 64;

    // Weights -> SMEM, transposed, bf16. Biases fp32.
    for (int idx = tid; idx < 128 * 128; idx += 256) {
        int k = idx >> 7, n = idx & 127;
        s.Wt1[n][k] = __float2bfloat16(W1[idx]);
        s.Wt2[n][k] = __float2bfloat16(W2[idx]);
    }
    if (tid < 128) { s.b1s[tid] = b1[tid]; s.b2s[tid] = b2[tid]; }

    // State in + out[0] = x copy.
    for (int idx = tid; idx < 64 * 128; idx += 256) {
        float v = x[row0 * 128 + idx];
        s.y[idx >> 7][idx & 127] = v;
        out[row0 * 128 + idx] = v;
    }
    __syncthreads();

    const float T   = t[0] / 10.0f;   // TIMESCALE = 10
    const float dt0 = g_dt0;

    const int lane = tid & 31, warp = tid >> 5;
    const int m0 = (warp & 3) * 16;
    const int n0 = (warp >> 2) * 64;
    const int gm = lane >> 2;
    const int qn = lane & 3;

    const float C2[1] = {1.f / 5.f};
    const float C3[2] = {3.f / 40.f, 9.f / 40.f};
    const float C4[3] = {44.f / 45.f, -56.f / 15.f, 32.f / 9.f};
    const float C5[4] = {19372.f / 6561.f, -25360.f / 2187.f, 64448.f / 6561.f, -212.f / 729.f};
    const float C6[5] = {9017.f / 3168.f, -355.f / 33.f, 46732.f / 5247.f, 49.f / 176.f, -5103.f / 18656.f};
    const float B1 = 35.f / 384.f, B3 = 500.f / 1113.f, B4 = 125.f / 192.f,
                B5 = -2187.f / 6784.f, B6 = 11.f / 84.f;

    float tt = 0.f;
    for (int it = 0; it < 48; it++) {
        float dt = fminf(fmaxf(T - tt, 0.f), dt0);
        if (!(dt > 0.f)) break;

        float c[8][4];
        build_arg<0>(s, tid, dt, C2);
        f_eval(s, c, m0, n0, gm, qn); store_k(s, c, 0, m0, n0, gm, qn);
        build_arg<1>(s, tid, dt, C2);
        f_eval(s, c, m0, n0, gm, qn); store_k(s, c, 1, m0, n0, gm, qn);
        build_arg<2>(s, tid, dt, C3);
        f_eval(s, c, m0, n0, gm, qn); store_k(s, c, 2, m0, n0, gm, qn);
        build_arg<3>(s, tid, dt, C4);
        f_eval(s, c, m0, n0, gm, qn); store_k(s, c, 3, m0, n0, gm, qn);
        build_arg<4>(s, tid, dt, C5);
        f_eval(s, c, m0, n0, gm, qn); store_k(s, c, 4, m0, n0, gm, qn);
        build_arg<5>(s, tid, dt, C6);
        f_eval(s, c, m0, n0, gm, qn);  // c = k6 (not stored)

        // y += dt*(B1 k1 + B3 k3 + B4 k4 + B5 k5 + B6 k6), fragment layout.
#pragma unroll
        for (int nt = 0; nt < 8; nt++) {
            int n = n0 + nt * 8 + qn * 2;
#pragma unroll
            for (int h = 0; h < 2; h++) {
                int m = m0 + gm + 8 * h;
                __nv_bfloat162 k1v = *(const __nv_bfloat162*)&s.kbuf[0][m][n];
                __nv_bfloat162 k3v = *(const __nv_bfloat162*)&s.kbuf[2][m][n];
                __nv_bfloat162 k4v = *(const __nv_bfloat162*)&s.kbuf[3][m][n];
                __nv_bfloat162 k5v = *(const __nv_bfloat162*)&s.kbuf[4][m][n];
                float u0 = B1 * __bfloat162float(k1v.x) + B3 * __bfloat162float(k3v.x)
                         + B4 * __bfloat162float(k4v.x) + B5 * __bfloat162float(k5v.x)
                         + B6 * c[nt][h * 2 + 0];
                float u1 = B1 * __bfloat162float(k1v.y) + B3 * __bfloat162float(k3v.y)
                         + B4 * __bfloat162float(k4v.y) + B5 * __bfloat162float(k5v.y)
                         + B6 * c[nt][h * 2 + 1];
                s.y[m][n]     += dt * u0;
                s.y[m][n + 1] += dt * u1;
            }
        }
        __syncthreads();
        tt += dt;
    }

    // out[1] = yT
    for (int idx = tid; idx < 64 * 128; idx += 256)
        out[8192 * 128 + row0 * 128 + idx] = s.y[idx >> 7][idx & 127];
}

// ---------------------------------------------------------------------------
// dt0: faithful fp32 port of initial_step_size on x[0].
// ---------------------------------------------------------------------------
__device__ __forceinline__ float bsum(float v, float* buf, int j) {
    buf[j] = v; __syncthreads();
    for (int sft = 64; sft > 0; sft >>= 1) {
        if (j < sft) buf[j] += buf[j + sft];
        __syncthreads();
    }
    float r = buf[0]; __syncthreads();
    return r;
}

__device__ __forceinline__ void mlp128(const float* yin, float* fout, float* hid,
                                       const float* W1, const float* b1,
                                       const float* W2, const float* b2, int j) {
    float acc = 0.f;
    for (int i = 0; i < 128; i++) acc += yin[i] * W1[i * 128 + j];
    hid[j] = tanhf(acc + b1[j]);
    __syncthreads();
    acc = 0.f;
    for (int i = 0; i < 128; i++) acc += hid[i] * W2[i * 128 + j];
    fout[j] = acc + b2[j];
    __syncthreads();
}

__global__ void dt0_kernel(const float* __restrict__ t, const float* __restrict__ x,
                           const float* __restrict__ W1, const float* __restrict__ b1,
                           const float* __restrict__ W2, const float* __restrict__ b2) {
    __shared__ float y0[128], f0v[128], f1v[128], y1s[128], hid[128], buf[128];
    int j = threadIdx.x;
    y0[j] = x[j];
    __syncthreads();

    mlp128(y0, f0v, hid, W1, b1, W2, b2, j);

    float scale = 1.4e-8f + fabsf(y0[j]) * 1.4e-8f;
    float a0 = y0[j] / scale;
    float d0 = sqrtf(bsum(a0 * a0, buf, j));
    float a1 = f0v[j] / scale;
    float d1 = sqrtf(bsum(a1 * a1, buf, j));
    float h0 = (d0 < 1e-5f || d1 < 1e-5f) ? 1e-6f : (0.01f * d0) / d1;

    y1s[j] = y0[j] + h0 * f0v[j];
    __syncthreads();
    mlp128(y1s, f1v, hid, W1, b1, W2, b2, j);

    float a2 = (f1v[j] - f0v[j]) / scale;
    float d2 = sqrtf(bsum(a2 * a2, buf, j)) / h0;
    float h1 = (d1 <= 1e-15f && d2 <= 1e-15f)
                   ? fmaxf(1e-6f, h0 * 1e-3f)
                   : powf(0.01f / (d1 + d2), 0.2f);
    if (j == 0) g_dt0 = fminf(100.0f * h0, h1);
}

extern "C" void kernel_launch(void* const* d_in, const int* in_sizes, int n_in,
                              void* d_out, int out_size) {
    const float* t  = (const float*)d_in[0];
    const float* x  = (const float*)d_in[1];
    const float* W1 = (const float*)d_in[2];
    const float* b1 = (const float*)d_in[3];
    const float* W2 = (const float*)d_in[4];
    const float* b2 = (const float*)d_in[5];
    float* out = (float*)d_out;

    dt0_kernel<<<1, 128>>>(t, x, W1, b1, W2, b2);

    int smem = (int)sizeof(Smem);
    cudaFuncSetAttribute(ode_kernel, cudaFuncAttributeMaxDynamicSharedMemorySize, smem);
    ode_kernel<<<128, 256, smem>>>(t, x, W1, b1, W2, b2, out);
}

// round 2
// speedup vs baseline: 1.3719x; 1.3719x over previous
#include <cuda_runtime.h>
#include <cuda_bf16.h>

// ---------------------------------------------------------------------------
// NeuralODE Dopri5, fully fused. R2: weights (both GEMM B-operands) and the
// fp32 state y live in REGISTERS; smem holds only k-stage buffers (bf16) and
// the stage-argument / hidden activations. Warp tiling 32m x 32n (2 m-pos x
// 4 n-pos), so each warp owns a fixed 32x32 element tile for the whole
// integration -> build_arg and the y-update are register ops + kbuf reads.
// ---------------------------------------------------------------------------

#define PADK 136                       // bf16 row stride (68 words, %32 == 4)
#define KBYTES (64 * PADK * 2)         // one 64x128(+pad) bf16 tile = 17408 B
typedef __nv_bfloat16 Row[PADK];

__device__ float g_dt0;

__device__ __forceinline__ float tanh_fast(float x) {
    float r;
    asm("tanh.approx.f32 %0, %1;" : "=f"(r) : "f"(x));
    return r;
}

__device__ __forceinline__ void mma_bf16(float* c, const unsigned* a, const unsigned* b) {
    asm volatile(
        "mma.sync.aligned.m16n8k16.row.col.f32.bf16.bf16.f32 "
        "{%0,%1,%2,%3}, {%4,%5,%6,%7}, {%8,%9}, {%0,%1,%2,%3};"
        : "+f"(c[0]), "+f"(c[1]), "+f"(c[2]), "+f"(c[3])
        : "r"(a[0]), "r"(a[1]), "r"(a[2]), "r"(a[3]), "r"(b[0]), "r"(b[1]));
}

// C[32x32 tile] = A[32 rows x 128] @ Wt^T + bias; B-fragments from registers.
__device__ __forceinline__ void gemm_reg(float c[2][4][4],
                                         const Row* __restrict__ A,
                                         const unsigned (&wb)[4][8][2],
                                         const float (&br)[4][2],
                                         int m0, int gm, int qn) {
#pragma unroll
    for (int mt = 0; mt < 2; mt++)
#pragma unroll
        for (int nt = 0; nt < 4; nt++) {
            c[mt][nt][0] = c[mt][nt][2] = br[nt][0];
            c[mt][nt][1] = c[mt][nt][3] = br[nt][1];
        }
#pragma unroll
    for (int kk = 0; kk < 8; kk++) {
        const int kb = kk * 16 + qn * 2;
        unsigned a[2][4];
#pragma unroll
        for (int mt = 0; mt < 2; mt++) {
            const int r = m0 + mt * 16 + gm;
            a[mt][0] = *(const unsigned*)&A[r][kb];
            a[mt][1] = *(const unsigned*)&A[r + 8][kb];
            a[mt][2] = *(const unsigned*)&A[r][kb + 8];
            a[mt][3] = *(const unsigned*)&A[r + 8][kb + 8];
        }
#pragma unroll
        for (int mt = 0; mt < 2; mt++)
#pragma unroll
            for (int nt = 0; nt < 4; nt++)
                mma_bf16(c[mt][nt], a[mt], wb[nt][kk]);
    }
}

// Stage arg (own tile only): Abuf = bf16(y + dt * sum_q kc[q]*k_q)
template <int NK>
__device__ __forceinline__ void build_arg(unsigned char* raw, Row* Abuf,
                                          const float (&y)[2][4][4],
                                          float dt, const float* kc,
                                          int m0, int n0, int gm, int qn) {
#pragma unroll
    for (int mt = 0; mt < 2; mt++)
#pragma unroll
        for (int nt = 0; nt < 4; nt++)
#pragma unroll
            for (int h = 0; h < 2; h++) {
                const int r = m0 + mt * 16 + gm + 8 * h;
                const int n = n0 + nt * 8 + qn * 2;
                float a0 = 0.f, a1 = 0.f;
#pragma unroll
                for (int q = 0; q < NK; q++) {
                    const Row* kq = (const Row*)(raw + q * KBYTES);
                    __nv_bfloat162 kv = *(const __nv_bfloat162*)&kq[r][n];
                    a0 += kc[q] * __bfloat162float(kv.x);
                    a1 += kc[q] * __bfloat162float(kv.y);
                }
                __nv_bfloat162 o;
                o.x = __float2bfloat16(y[mt][nt][2 * h]     + dt * a0);
                o.y = __float2bfloat16(y[mt][nt][2 * h + 1] + dt * a1);
                *(__nv_bfloat162*)&Abuf[r][n] = o;
            }
}

template <bool DO_TANH>
__device__ __forceinline__ void store_tile(Row* dst, const float c[2][4][4],
                                           int m0, int n0, int gm, int qn) {
#pragma unroll
    for (int mt = 0; mt < 2; mt++)
#pragma unroll
        for (int nt = 0; nt < 4; nt++) {
            const int r = m0 + mt * 16 + gm;
            const int n = n0 + nt * 8 + qn * 2;
            __nv_bfloat162 v0, v1;
            if (DO_TANH) {
                v0.x = __float2bfloat16(tanh_fast(c[mt][nt][0]));
                v0.y = __float2bfloat16(tanh_fast(c[mt][nt][1]));
                v1.x = __float2bfloat16(tanh_fast(c[mt][nt][2]));
                v1.y = __float2bfloat16(tanh_fast(c[mt][nt][3]));
            } else {
                v0.x = __float2bfloat16(c[mt][nt][0]);
                v0.y = __float2bfloat16(c[mt][nt][1]);
                v1.x = __float2bfloat16(c[mt][nt][2]);
                v1.y = __float2bfloat16(c[mt][nt][3]);
            }
            *(__nv_bfloat162*)&dst[r][n]     = v0;
            *(__nv_bfloat162*)&dst[r + 8][n] = v1;
        }
}

__global__ void __launch_bounds__(256, 1)
ode_kernel(const float* __restrict__ t, const float* __restrict__ x,
           const float* __restrict__ W1, const float* __restrict__ b1,
           const float* __restrict__ W2, const float* __restrict__ b2,
           float* __restrict__ out) {
    extern __shared__ unsigned char raw[];
    // smem map: [0 .. 5*KBYTES) = kbuf[0..4]; then Abuf; then Hbuf.
    Row* Abuf = (Row*)(raw + 5 * KBYTES);
    Row* Hbuf = (Row*)(raw + 6 * KBYTES);
    // init-time staging (overlaps kbuf region, dead before first kbuf write):
    Row*   Wst   = (Row*)raw;                 // Wt1 [128][PADK], Wt2 follows
    Row*   Wst2  = (Row*)(raw + 128 * PADK * 2);
    float* bstag = (float*)(raw + 5 * KBYTES);  // 256 floats in Abuf region

    const int tid  = threadIdx.x;
    const int row0 = blockIdx.x * 64;
    const int lane = tid & 31, warp = tid >> 5;
    const int m0 = (warp & 1) * 32;       // 2 m-positions
    const int n0 = (warp >> 1) * 32;      // 4 n-positions
    const int gm = lane >> 2;             // 0..7
    const int qn = lane & 3;              // 0..3

    // ---- stage weights (transposed, bf16) + biases into smem ----
    for (int idx = tid; idx < 128 * 128; idx += 256) {
        int k = idx >> 7, n = idx & 127;
        Wst[n][k]  = __float2bfloat16(W1[idx]);
        Wst2[n][k] = __float2bfloat16(W2[idx]);
    }
    if (tid < 128) { bstag[tid] = b1[tid]; bstag[128 + tid] = b2[tid]; }
    // out[0] = x (coalesced copy)
    for (int idx = tid; idx < 64 * 128; idx += 256)
        out[row0 * 128 + idx] = x[row0 * 128 + idx];
    __syncthreads();

    // ---- load weight B-fragments + biases into registers ----
    unsigned wb1[4][8][2], wb2[4][8][2];
    float br1[4][2], br2[4][2];
#pragma unroll
    for (int nt = 0; nt < 4; nt++) {
        const int n = n0 + nt * 8 + gm;
#pragma unroll
        for (int kk = 0; kk < 8; kk++) {
            const int kb = kk * 16 + qn * 2;
            wb1[nt][kk][0] = *(const unsigned*)&Wst[n][kb];
            wb1[nt][kk][1] = *(const unsigned*)&Wst[n][kb + 8];
            wb2[nt][kk][0] = *(const unsigned*)&Wst2[n][kb];
            wb2[nt][kk][1] = *(const unsigned*)&Wst2[n][kb + 8];
        }
        const int nb = n0 + nt * 8 + qn * 2;
        br1[nt][0] = bstag[nb];       br1[nt][1] = bstag[nb + 1];
        br2[nt][0] = bstag[128 + nb]; br2[nt][1] = bstag[128 + nb + 1];
    }

    // ---- load state y into registers (C-fragment layout) ----
    float yreg[2][4][4];
    {
        const float* xr = x + row0 * 128;
#pragma unroll
        for (int mt = 0; mt < 2; mt++)
#pragma unroll
            for (int nt = 0; nt < 4; nt++)
#pragma unroll
                for (int h = 0; h < 2; h++) {
                    const int r = m0 + mt * 16 + gm + 8 * h;
                    const int n = n0 + nt * 8 + qn * 2;
                    float2 v = *(const float2*)&xr[r * 128 + n];
                    yreg[mt][nt][2 * h] = v.x;
                    yreg[mt][nt][2 * h + 1] = v.y;
                }
    }
    __syncthreads();   // staging regions now dead; kbuf may be written

    const float T   = t[0] / 10.0f;    // TIMESCALE = 10
    const float dt0 = g_dt0;

    const float C2[1] = {1.f / 5.f};
    const float C3[2] = {3.f / 40.f, 9.f / 40.f};
    const float C4[3] = {44.f / 45.f, -56.f / 15.f, 32.f / 9.f};
    const float C5[4] = {19372.f / 6561.f, -25360.f / 2187.f, 64448.f / 6561.f, -212.f / 729.f};
    const float C6[5] = {9017.f / 3168.f, -355.f / 33.f, 46732.f / 5247.f, 49.f / 176.f, -5103.f / 18656.f};
    const float B1 = 35.f / 384.f, B3 = 500.f / 1113.f, B4 = 125.f / 192.f,
                B5 = -2187.f / 6784.f, B6 = 11.f / 84.f;

    float c[2][4][4];
    float tt = 0.f;
    for (int it = 0; it < 48; it++) {
        float dt = fminf(fmaxf(T - tt, 0.f), dt0);
        if (!(dt > 0.f)) break;

#define STAGE(NK, COEF, KQ)                                                  \
        build_arg<NK>(raw, Abuf, yreg, dt, COEF, m0, n0, gm, qn);            \
        __syncthreads();                                                     \
        gemm_reg(c, Abuf, wb1, br1, m0, gm, qn);                             \
        store_tile<true>(Hbuf, c, m0, n0, gm, qn);                           \
        __syncthreads();                                                     \
        gemm_reg(c, Hbuf, wb2, br2, m0, gm, qn);                             \
        if (KQ >= 0) {                                                       \
            store_tile<false>((Row*)(raw + KQ * KBYTES), c, m0, n0, gm, qn); \
            __syncthreads();                                                 \
        }

        STAGE(0, C2, 0)
        STAGE(1, C2, 1)
        STAGE(2, C3, 2)
        STAGE(3, C4, 3)
        STAGE(4, C5, 4)
        STAGE(5, C6, -1)   // c = k6, kept in registers
#undef STAGE

        // y += dt*(B1 k1 + B3 k3 + B4 k4 + B5 k5 + B6 k6) — own tile, ks
        // written by this same warp, no sync needed before reading.
        const Row* k1b = (const Row*)(raw + 0 * KBYTES);
        const Row* k3b = (const Row*)(raw + 2 * KBYTES);
        const Row* k4b = (const Row*)(raw + 3 * KBYTES);
        const Row* k5b = (const Row*)(raw + 4 * KBYTES);
#pragma unroll
        for (int mt = 0; mt < 2; mt++)
#pragma unroll
            for (int nt = 0; nt < 4; nt++)
#pragma unroll
                for (int h = 0; h < 2; h++) {
                    const int r = m0 + mt * 16 + gm + 8 * h;
                    const int n = n0 + nt * 8 + qn * 2;
                    __nv_bfloat162 k1v = *(const __nv_bfloat162*)&k1b[r][n];
                    __nv_bfloat162 k3v = *(const __nv_bfloat162*)&k3b[r][n];
                    __nv_bfloat162 k4v = *(const __nv_bfloat162*)&k4b[r][n];
                    __nv_bfloat162 k5v = *(const __nv_bfloat162*)&k5b[r][n];
                    float u0 = B1 * __bfloat162float(k1v.x) + B3 * __bfloat162float(k3v.x)
                             + B4 * __bfloat162float(k4v.x) + B5 * __bfloat162float(k5v.x)
                             + B6 * c[mt][nt][2 * h];
                    float u1 = B1 * __bfloat162float(k1v.y) + B3 * __bfloat162float(k3v.y)
                             + B4 * __bfloat162float(k4v.y) + B5 * __bfloat162float(k5v.y)
                             + B6 * c[mt][nt][2 * h + 1];
                    yreg[mt][nt][2 * h]     += dt * u0;
                    yreg[mt][nt][2 * h + 1] += dt * u1;
                }
        __syncthreads();   // Abuf/Hbuf fully consumed before next stage write
        tt += dt;
    }

    // ---- out[1] = yT (direct fragment-layout stores) ----
    float* o1 = out + 8192 * 128 + row0 * 128;
#pragma unroll
    for (int mt = 0; mt < 2; mt++)
#pragma unroll
        for (int nt = 0; nt < 4; nt++)
#pragma unroll
            for (int h = 0; h < 2; h++) {
                const int r = m0 + mt * 16 + gm + 8 * h;
                const int n = n0 + nt * 8 + qn * 2;
                float2 v;
                v.x = yreg[mt][nt][2 * h];
                v.y = yreg[mt][nt][2 * h + 1];
                *(float2*)&o1[r * 128 + n] = v;
            }
}

// ---------------------------------------------------------------------------
// dt0: faithful fp32 port of initial_step_size on x[0]. (unchanged)
// ---------------------------------------------------------------------------
__device__ __forceinline__ float bsum(float v, float* buf, int j) {
    buf[j] = v; __syncthreads();
    for (int sft = 64; sft > 0; sft >>= 1) {
        if (j < sft) buf[j] += buf[j + sft];
        __syncthreads();
    }
    float r = buf[0]; __syncthreads();
    return r;
}

__device__ __forceinline__ void mlp128(const float* yin, float* fout, float* hid,
                                       const float* W1, const float* b1,
                                       const float* W2, const float* b2, int j) {
    float acc = 0.f;
    for (int i = 0; i < 128; i++) acc += yin[i] * W1[i * 128 + j];
    hid[j] = tanhf(acc + b1[j]);
    __syncthreads();
    acc = 0.f;
    for (int i = 0; i < 128; i++) acc += hid[i] * W2[i * 128 + j];
    fout[j] = acc + b2[j];
    __syncthreads();
}

__global__ void dt0_kernel(const float* __restrict__ t, const float* __restrict__ x,
                           const float* __restrict__ W1, const float* __restrict__ b1,
                           const float* __restrict__ W2, const float* __restrict__ b2) {
    __shared__ float y0[128], f0v[128], f1v[128], y1s[128], hid[128], buf[128];
    int j = threadIdx.x;
    y0[j] = x[j];
    __syncthreads();

    mlp128(y0, f0v, hid, W1, b1, W2, b2, j);

    float scale = 1.4e-8f + fabsf(y0[j]) * 1.4e-8f;
    float a0 = y0[j] / scale;
    float d0 = sqrtf(bsum(a0 * a0, buf, j));
    float a1 = f0v[j] / scale;
    float d1 = sqrtf(bsum(a1 * a1, buf, j));
    float h0 = (d0 < 1e-5f || d1 < 1e-5f) ? 1e-6f : (0.01f * d0) / d1;

    y1s[j] = y0[j] + h0 * f0v[j];
    __syncthreads();
    mlp128(y1s, f1v, hid, W1, b1, W2, b2, j);

    float a2 = (f1v[j] - f0v[j]) / scale;
    float d2 = sqrtf(bsum(a2 * a2, buf, j)) / h0;
    float h1 = (d1 <= 1e-15f && d2 <= 1e-15f)
                   ? fmaxf(1e-6f, h0 * 1e-3f)
                   : powf(0.01f / (d1 + d2), 0.2f);
    if (j == 0) g_dt0 = fminf(100.0f * h0, h1);
}

extern "C" void kernel_launch(void* const* d_in, const int* in_sizes, int n_in,
                              void* d_out, int out_size) {
    const float* t  = (const float*)d_in[0];
    const float* x  = (const float*)d_in[1];
    const float* W1 = (const float*)d_in[2];
    const float* b1 = (const float*)d_in[3];
    const float* W2 = (const float*)d_in[4];
    const float* b2 = (const float*)d_in[5];
    float* out = (float*)d_out;

    dt0_kernel<<<1, 128>>>(t, x, W1, b1, W2, b2);

    int smem = 7 * KBYTES;   // 5 kbufs + Abuf + Hbuf = 121856 B
    cudaFuncSetAttribute(ode_kernel, cudaFuncAttributeMaxDynamicSharedMemorySize, smem);
    ode_kernel<<<128, 256, smem>>>(t, x, W1, b1, W2, b2, out);
}

// round 3
// speedup vs baseline: 1.4237x; 1.0378x over previous
#include <cuda_runtime.h>
#include <cuda_bf16.h>

// ---------------------------------------------------------------------------
// NeuralODE Dopri5, fully fused persistent kernel. R3:
//  - 512 threads / 16 warps per CTA, warp tile 32m x 16n
//    -> weight frags (64 regs) + state y (16 regs) fit under the 128-reg cap,
//       no spills, 2x warps per scheduler.
//  - named barriers scoped to the 8-warp m-row group (256 threads)
//  - double-buffered Abuf/Hbuf -> 2 barriers per stage (was 3)
//  - ldmatrix.x4 for A fragments
// ---------------------------------------------------------------------------

#define PADK 136                       // bf16 row stride (272 B, multiple of 16)
#define KBYTES (64 * PADK * 2)         // one 64x128(+pad) bf16 tile = 17408 B
typedef __nv_bfloat16 Row[PADK];

__device__ float g_dt0;

__device__ __forceinline__ float tanh_fast(float x) {
    float r;
    asm("tanh.approx.f32 %0, %1;" : "=f"(r) : "f"(x));
    return r;
}

__device__ __forceinline__ void mma_bf16(float* c, const unsigned* a, const unsigned* b) {
    asm volatile(
        "mma.sync.aligned.m16n8k16.row.col.f32.bf16.bf16.f32 "
        "{%0,%1,%2,%3}, {%4,%5,%6,%7}, {%8,%9}, {%0,%1,%2,%3};"
        : "+f"(c[0]), "+f"(c[1]), "+f"(c[2]), "+f"(c[3])
        : "r"(a[0]), "r"(a[1]), "r"(a[2]), "r"(a[3]), "r"(b[0]), "r"(b[1]));
}

__device__ __forceinline__ void ldsm_x4(unsigned a[4], unsigned addr) {
    asm volatile("ldmatrix.sync.aligned.m8n8.x4.shared.b16 {%0,%1,%2,%3}, [%4];"
                 : "=r"(a[0]), "=r"(a[1]), "=r"(a[2]), "=r"(a[3]) : "r"(addr));
}

// C[32x16 tile] = A[32 rows x 128] @ Wt^T + bias. A via ldmatrix, B from regs.
__device__ __forceinline__ void gemm_reg(float c[2][2][4], unsigned abase,
                                         const unsigned (&wb)[2][8][2],
                                         const float (&br)[2][2]) {
#pragma unroll
    for (int mt = 0; mt < 2; mt++)
#pragma unroll
        for (int nt = 0; nt < 2; nt++) {
            c[mt][nt][0] = c[mt][nt][2] = br[nt][0];
            c[mt][nt][1] = c[mt][nt][3] = br[nt][1];
        }
#pragma unroll
    for (int kk = 0; kk < 8; kk++) {
        unsigned a[2][4];
#pragma unroll
        for (int mt = 0; mt < 2; mt++)
            ldsm_x4(a[mt], abase + mt * (16 * PADK * 2) + kk * 32);
#pragma unroll
        for (int mt = 0; mt < 2; mt++)
#pragma unroll
            for (int nt = 0; nt < 2; nt++)
                mma_bf16(c[mt][nt], a[mt], wb[nt][kk]);
    }
}

// Stage arg (own 32x16 tile): Abuf = bf16(y + dt * sum_q kc[q]*k_q)
template <int NK>
__device__ __forceinline__ void build_arg(unsigned char* raw, Row* Abuf,
                                          const float (&y)[2][2][4],
                                          float dt, const float* kc,
                                          int m0, int n0, int gm, int qn) {
#pragma unroll
    for (int mt = 0; mt < 2; mt++)
#pragma unroll
        for (int nt = 0; nt < 2; nt++)
#pragma unroll
            for (int h = 0; h < 2; h++) {
                const int r = m0 + mt * 16 + gm + 8 * h;
                const int n = n0 + nt * 8 + qn * 2;
                float a0 = 0.f, a1 = 0.f;
#pragma unroll
                for (int q = 0; q < NK; q++) {
                    const Row* kq = (const Row*)(raw + q * KBYTES);
                    __nv_bfloat162 kv = *(const __nv_bfloat162*)&kq[r][n];
                    a0 += kc[q] * __bfloat162float(kv.x);
                    a1 += kc[q] * __bfloat162float(kv.y);
                }
                __nv_bfloat162 o;
                o.x = __float2bfloat16(y[mt][nt][2 * h]     + dt * a0);
                o.y = __float2bfloat16(y[mt][nt][2 * h + 1] + dt * a1);
                *(__nv_bfloat162*)&Abuf[r][n] = o;
            }
}

template <bool DO_TANH>
__device__ __forceinline__ void store_tile(Row* dst, const float c[2][2][4],
                                           int m0, int n0, int gm, int qn) {
#pragma unroll
    for (int mt = 0; mt < 2; mt++)
#pragma unroll
        for (int nt = 0; nt < 2; nt++) {
            const int r = m0 + mt * 16 + gm;
            const int n = n0 + nt * 8 + qn * 2;
            __nv_bfloat162 v0, v1;
            if (DO_TANH) {
                v0.x = __float2bfloat16(tanh_fast(c[mt][nt][0]));
                v0.y = __float2bfloat16(tanh_fast(c[mt][nt][1]));
                v1.x = __float2bfloat16(tanh_fast(c[mt][nt][2]));
                v1.y = __float2bfloat16(tanh_fast(c[mt][nt][3]));
            } else {
                v0.x = __float2bfloat16(c[mt][nt][0]);
                v0.y = __float2bfloat16(c[mt][nt][1]);
                v1.x = __float2bfloat16(c[mt][nt][2]);
                v1.y = __float2bfloat16(c[mt][nt][3]);
            }
            *(__nv_bfloat162*)&dst[r][n]     = v0;
            *(__nv_bfloat162*)&dst[r + 8][n] = v1;
        }
}

__global__ void __launch_bounds__(512, 1)
ode_kernel(const float* __restrict__ t, const float* __restrict__ x,
           const float* __restrict__ W1, const float* __restrict__ b1,
           const float* __restrict__ W2, const float* __restrict__ b2,
           float* __restrict__ out) {
    extern __shared__ unsigned char raw[];
    // smem: kbuf[0..4] | Abuf0 | Abuf1 | Hbuf0 | Hbuf1   (9 tiles)
    Row* Abufs[2] = { (Row*)(raw + 5 * KBYTES), (Row*)(raw + 6 * KBYTES) };
    Row* Hbufs[2] = { (Row*)(raw + 7 * KBYTES), (Row*)(raw + 8 * KBYTES) };
    // init staging (dead after init): weights in kbuf region, biases in Abuf0
    Row*   Wst   = (Row*)raw;
    Row*   Wst2  = (Row*)(raw + 2 * KBYTES);
    float* bstag = (float*)(raw + 5 * KBYTES);

    const int tid  = threadIdx.x;
    const int row0 = blockIdx.x * 64;
    const int lane = tid & 31, warp = tid >> 5;
    const int m0 = (warp & 1) * 32;        // 2 m-groups
    const int n0 = (warp >> 1) * 16;       // 8 n-positions
    const int gm = lane >> 2;              // 0..7
    const int qn = lane & 3;               // 0..3
    const int barid = 1 + (warp & 1);      // named barrier per m-group
    const int lrow = lane & 15;            // ldmatrix lane row
    const int lcol = (lane >> 4) * 8;      // ldmatrix lane k-offset

#define BARG() asm volatile("bar.sync %0, 256;" :: "r"(barid) : "memory")

    // ---- stage weights (transposed, bf16) + biases into smem ----
    for (int idx = tid; idx < 128 * 128; idx += 512) {
        int k = idx >> 7, n = idx & 127;
        Wst[n][k]  = __float2bfloat16(W1[idx]);
        Wst2[n][k] = __float2bfloat16(W2[idx]);
    }
    if (tid < 128) { bstag[tid] = b1[tid]; bstag[128 + tid] = b2[tid]; }
    for (int idx = tid; idx < 64 * 128; idx += 512)
        out[row0 * 128 + idx] = x[row0 * 128 + idx];
    __syncthreads();

    // ---- weight B-fragments + biases -> registers ----
    unsigned wb1[2][8][2], wb2[2][8][2];
    float br1[2][2], br2[2][2];
#pragma unroll
    for (int nt = 0; nt < 2; nt++) {
        const int n = n0 + nt * 8 + gm;
#pragma unroll
        for (int kk = 0; kk < 8; kk++) {
            const int kb = kk * 16 + qn * 2;
            wb1[nt][kk][0] = *(const unsigned*)&Wst[n][kb];
            wb1[nt][kk][1] = *(const unsigned*)&Wst[n][kb + 8];
            wb2[nt][kk][0] = *(const unsigned*)&Wst2[n][kb];
            wb2[nt][kk][1] = *(const unsigned*)&Wst2[n][kb + 8];
        }
        const int nb = n0 + nt * 8 + qn * 2;
        br1[nt][0] = bstag[nb];       br1[nt][1] = bstag[nb + 1];
        br2[nt][0] = bstag[128 + nb]; br2[nt][1] = bstag[128 + nb + 1];
    }

    // ---- state y -> registers (C-fragment layout) ----
    float yreg[2][2][4];
    {
        const float* xr = x + row0 * 128;
#pragma unroll
        for (int mt = 0; mt < 2; mt++)
#pragma unroll
            for (int nt = 0; nt < 2; nt++)
#pragma unroll
                for (int h = 0; h < 2; h++) {
                    const int r = m0 + mt * 16 + gm + 8 * h;
                    const int n = n0 + nt * 8 + qn * 2;
                    float2 v = *(const float2*)&xr[r * 128 + n];
                    yreg[mt][nt][2 * h]     = v.x;
                    yreg[mt][nt][2 * h + 1] = v.y;
                }
    }
    __syncthreads();   // staging dead; kbuf/Abuf writable

    const float T   = t[0] / 10.0f;    // TIMESCALE = 10
    const float dt0 = g_dt0;

    // per-warp ldmatrix base byte offset within a tile
    const unsigned aoff = (unsigned)(((m0 + lrow) * PADK + lcol) * 2);
    const unsigned Ab[2] = { (unsigned)__cvta_generic_to_shared(Abufs[0]) + aoff,
                             (unsigned)__cvta_generic_to_shared(Abufs[1]) + aoff };
    const unsigned Hb[2] = { (unsigned)__cvta_generic_to_shared(Hbufs[0]) + aoff,
                             (unsigned)__cvta_generic_to_shared(Hbufs[1]) + aoff };

    const float C2[1] = {1.f / 5.f};
    const float C3[2] = {3.f / 40.f, 9.f / 40.f};
    const float C4[3] = {44.f / 45.f, -56.f / 15.f, 32.f / 9.f};
    const float C5[4] = {19372.f / 6561.f, -25360.f / 2187.f, 64448.f / 6561.f, -212.f / 729.f};
    const float C6[5] = {9017.f / 3168.f, -355.f / 33.f, 46732.f / 5247.f, 49.f / 176.f, -5103.f / 18656.f};
    const float B1 = 35.f / 384.f, B3 = 500.f / 1113.f, B4 = 125.f / 192.f,
                B5 = -2187.f / 6784.f, B6 = 11.f / 84.f;

    float c[2][2][4];
    float tt = 0.f;
    int p = 0;                          // ping-pong parity, flips per stage
    for (int it = 0; it < 48; it++) {
        float dt = fminf(fmaxf(T - tt, 0.f), dt0);
        if (!(dt > 0.f)) break;

#define STAGE(NK, COEF, KQ)                                                  \
        build_arg<NK>(raw, Abufs[p], yreg, dt, COEF, m0, n0, gm, qn);        \
        BARG();                          /* Abuf[p] ready (m-group) */       \
        gemm_reg(c, Ab[p], wb1, br1);                                        \
        store_tile<true>(Hbufs[p], c, m0, n0, gm, qn);                       \
        BARG();                          /* Hbuf[p] ready; Abuf[p] free */   \
        gemm_reg(c, Hb[p], wb2, br2);                                        \
        if (KQ >= 0)                                                         \
            store_tile<false>((Row*)(raw + KQ * KBYTES), c, m0, n0, gm, qn); \
        p ^= 1;

        STAGE(0, C2, 0)
        STAGE(1, C2, 1)
        STAGE(2, C3, 2)
        STAGE(3, C4, 3)
        STAGE(4, C5, 4)
        STAGE(5, C6, -1)   // c = k6, stays in registers
#undef STAGE

        // y += dt*(B1 k1 + B3 k3 + B4 k4 + B5 k5 + B6 k6); all reads are
        // own-tile values this warp wrote -> no sync needed.
        const Row* k1b = (const Row*)(raw + 0 * KBYTES);
        const Row* k3b = (const Row*)(raw + 2 * KBYTES);
        const Row* k4b = (const Row*)(raw + 3 * KBYTES);
        const Row* k5b = (const Row*)(raw + 4 * KBYTES);
#pragma unroll
        for (int mt = 0; mt < 2; mt++)
#pragma unroll
            for (int nt = 0; nt < 2; nt++)
#pragma unroll
                for (int h = 0; h < 2; h++) {
                    const int r = m0 + mt * 16 + gm + 8 * h;
                    const int n = n0 + nt * 8 + qn * 2;
                    __nv_bfloat162 k1v = *(const __nv_bfloat162*)&k1b[r][n];
                    __nv_bfloat162 k3v = *(const __nv_bfloat162*)&k3b[r][n];
                    __nv_bfloat162 k4v = *(const __nv_bfloat162*)&k4b[r][n];
                    __nv_bfloat162 k5v = *(const __nv_bfloat162*)&k5b[r][n];
                    float u0 = B1 * __bfloat162float(k1v.x) + B3 * __bfloat162float(k3v.x)
                             + B4 * __bfloat162float(k4v.x) + B5 * __bfloat162float(k5v.x)
                             + B6 * c[mt][nt][2 * h];
                    float u1 = B1 * __bfloat162float(k1v.y) + B3 * __bfloat162float(k3v.y)
                             + B4 * __bfloat162float(k4v.y) + B5 * __bfloat162float(k5v.y)
                             + B6 * c[mt][nt][2 * h + 1];
                    yreg[mt][nt][2 * h]     += dt * u0;
                    yreg[mt][nt][2 * h + 1] += dt * u1;
                }
        tt += dt;
    }

    // ---- out[1] = yT ----
    float* o1 = out + 8192 * 128 + row0 * 128;
#pragma unroll
    for (int mt = 0; mt < 2; mt++)
#pragma unroll
        for (int nt = 0; nt < 2; nt++)
#pragma unroll
            for (int h = 0; h < 2; h++) {
                const int r = m0 + mt * 16 + gm + 8 * h;
                const int n = n0 + nt * 8 + qn * 2;
                float2 v;
                v.x = yreg[mt][nt][2 * h];
                v.y = yreg[mt][nt][2 * h + 1];
                *(float2*)&o1[r * 128 + n] = v;
            }
#undef BARG
}

// ---------------------------------------------------------------------------
// dt0: faithful fp32 port of initial_step_size on x[0]. (unchanged)
// ---------------------------------------------------------------------------
__device__ __forceinline__ float bsum(float v, float* buf, int j) {
    buf[j] = v; __syncthreads();
    for (int sft = 64; sft > 0; sft >>= 1) {
        if (j < sft) buf[j] += buf[j + sft];
        __syncthreads();
    }
    float r = buf[0]; __syncthreads();
    return r;
}

__device__ __forceinline__ void mlp128(const float* yin, float* fout, float* hid,
                                       const float* W1, const float* b1,
                                       const float* W2, const float* b2, int j) {
    float acc = 0.f;
    for (int i = 0; i < 128; i++) acc += yin[i] * W1[i * 128 + j];
    hid[j] = tanhf(acc + b1[j]);
    __syncthreads();
    acc = 0.f;
    for (int i = 0; i < 128; i++) acc += hid[i] * W2[i * 128 + j];
    fout[j] = acc + b2[j];
    __syncthreads();
}

__global__ void dt0_kernel(const float* __restrict__ t, const float* __restrict__ x,
                           const float* __restrict__ W1, const float* __restrict__ b1,
                           const float* __restrict__ W2, const float* __restrict__ b2) {
    __shared__ float y0[128], f0v[128], f1v[128], y1s[128], hid[128], buf[128];
    int j = threadIdx.x;
    y0[j] = x[j];
    __syncthreads();

    mlp128(y0, f0v, hid, W1, b1, W2, b2, j);

    float scale = 1.4e-8f + fabsf(y0[j]) * 1.4e-8f;
    float a0 = y0[j] / scale;
    float d0 = sqrtf(bsum(a0 * a0, buf, j));
    float a1 = f0v[j] / scale;
    float d1 = sqrtf(bsum(a1 * a1, buf, j));
    float h0 = (d0 < 1e-5f || d1 < 1e-5f) ? 1e-6f : (0.01f * d0) / d1;

    y1s[j] = y0[j] + h0 * f0v[j];
    __syncthreads();
    mlp128(y1s, f1v, hid, W1, b1, W2, b2, j);

    float a2 = (f1v[j] - f0v[j]) / scale;
    float d2 = sqrtf(bsum(a2 * a2, buf, j)) / h0;
    float h1 = (d1 <= 1e-15f && d2 <= 1e-15f)
                   ? fmaxf(1e-6f, h0 * 1e-3f)
                   : powf(0.01f / (d1 + d2), 0.2f);
    if (j == 0) g_dt0 = fminf(100.0f * h0, h1);
}

extern "C" void kernel_launch(void* const* d_in, const int* in_sizes, int n_in,
                              void* d_out, int out_size) {
    const float* t  = (const float*)d_in[0];
    const float* x  = (const float*)d_in[1];
    const float* W1 = (const float*)d_in[2];
    const float* b1 = (const float*)d_in[3];
    const float* W2 = (const float*)d_in[4];
    const float* b2 = (const float*)d_in[5];
    float* out = (float*)d_out;

    dt0_kernel<<<1, 128>>>(t, x, W1, b1, W2, b2);

    int smem = 9 * KBYTES;   // 5 kbufs + 2 Abuf + 2 Hbuf = 156672 B
    cudaFuncSetAttribute(ode_kernel, cudaFuncAttributeMaxDynamicSharedMemorySize, smem);
    ode_kernel<<<128, 512, smem>>>(t, x, W1, b1, W2, b2, out);
}